// round 9
// baseline (speedup 1.0000x reference)
#include <cuda_runtime.h>
#include <math.h>

#define THRE_TIMES 5.0f
#define THRE_POINT 1000.0f
#define RPT 4   // output rows per thread

typedef unsigned long long u64;

__device__ __forceinline__ u64 pk2(float lo, float hi) {
    u64 r; asm("mov.b64 %0, {%1, %2};" : "=l"(r) : "f"(lo), "f"(hi)); return r;
}
__device__ __forceinline__ void upk2(u64 v, float& lo, float& hi) {
    asm("mov.b64 {%0, %1}, %2;" : "=f"(lo), "=f"(hi) : "l"(v));
}
__device__ __forceinline__ u64 addx2(u64 a, u64 b) {
    u64 r; asm("add.rn.f32x2 %0, %1, %2;" : "=l"(r) : "l"(a), "l"(b)); return r;
}
__device__ __forceinline__ u64 mulx2(u64 a, u64 b) {
    u64 r; asm("mul.rn.f32x2 %0, %1, %2;" : "=l"(r) : "l"(a), "l"(b)); return r;
}

// ---------------------------------------------------------------------------
// Warp = 128 contiguous columns (32 lanes x float4). Halos via shuffle.
// Interior: packed f32x2 math, no persistent u64 arrays (register-lean).
// Requires W % 128 == 0, H % (8*RPT) == 0.
// ---------------------------------------------------------------------------
__global__ __launch_bounds__(256, 4) void dpr_shfl_kernel(
    const float* __restrict__ img, float* __restrict__ out, int H, int W)
{
    const int lane = threadIdx.x;                       // 0..31
    const int c4   = (blockIdx.x * 32 + lane) * 4;
    const int r0   = (blockIdx.y * blockDim.y + threadIdx.y) * RPT;

    const bool fast = (r0 >= 1) && (r0 + RPT + 1 <= H) &&
                      (blockIdx.x > 0) && (blockIdx.x < gridDim.x - 1);

    if (fast) {
        // ---------------- interior fast path ----------------
        float4 arr[RPT + 2];
        float  lft[RPT + 2], rgt[RPT + 2];
        const float* base = img + (size_t)(r0 - 1) * W + c4;

        // Edge-lane halo loads first: independent, overlap with the batch below.
        float eh[RPT + 2];
        if (lane == 0) {
#pragma unroll
            for (int s = 0; s < RPT + 2; ++s) eh[s] = __ldg(base + (size_t)s * W - 1);
        } else if (lane == 31) {
#pragma unroll
            for (int s = 0; s < RPT + 2; ++s) eh[s] = __ldg(base + (size_t)s * W + 4);
        }

#pragma unroll
        for (int s = 0; s < RPT + 2; ++s)
            arr[s] = *reinterpret_cast<const float4*>(base + (size_t)s * W);

#pragma unroll
        for (int s = 0; s < RPT + 2; ++s) {
            float lw = __shfl_up_sync(0xffffffffu, arr[s].w, 1);
            float rw = __shfl_down_sync(0xffffffffu, arr[s].x, 1);
            if (lane == 0)  lw = eh[s];
            if (lane == 31) rw = eh[s];
            lft[s] = lw; rgt[s] = rw;
        }

        const u64 PK59  = pk2(THRE_TIMES / 9.0f, THRE_TIMES / 9.0f);  // 5/9
        const u64 PK025 = pk2(0.25f, 0.25f);

#pragma unroll
        for (int ri = 0; ri < RPT; ++ri) {
            const float4 up  = arr[ri];
            const float4 mid = arr[ri + 1];
            const float4 dn  = arr[ri + 2];

            // horizontal 3-sums (packed), built inline from arr/halos
            u64 hsA[3], hsB[3];
#pragma unroll
            for (int k = 0; k < 3; ++k) {
                const float4 a = arr[ri + k];
                u64 yz = pk2(a.y, a.z);
                u64 lx = pk2(lft[ri + k], a.x);
                u64 xy = pk2(a.x, a.y);
                u64 zw = pk2(a.z, a.w);
                u64 wr = pk2(a.w, rgt[ri + k]);
                hsA[k] = addx2(addx2(lx, xy), yz);   // cols 0,1
                hsB[k] = addx2(addx2(yz, zw), wr);   // cols 2,3
            }

            u64 upA = pk2(up.x, up.y),  upB = pk2(up.z, up.w);
            u64 dnA = pk2(dn.x, dn.y),  dnB = pk2(dn.z, dn.w);
            u64 myz = pk2(mid.y, mid.z);

            // ns_j = ((up_j + dn_j) + left_j) + right_j
            u64 nsA = addx2(addx2(addx2(upA, dnA), pk2(lft[ri + 1], mid.x)), myz);
            u64 nsB = addx2(addx2(addx2(upB, dnB), myz), pk2(mid.w, rgt[ri + 1]));

            u64 sum9A = addx2(addx2(hsA[0], hsA[1]), hsA[2]);
            u64 sum9B = addx2(addx2(hsB[0], hsB[1]), hsB[2]);
            u64 thrA = mulx2(sum9A, PK59);
            u64 thrB = mulx2(sum9B, PK59);
            u64 repA = mulx2(nsA, PK025);
            u64 repB = mulx2(nsB, PK025);

            float t0, t1, t2, t3, p0, p1, p2, p3;
            upk2(thrA, t0, t1); upk2(thrB, t2, t3);
            upk2(repA, p0, p1); upk2(repB, p2, p3);

            float o0 = (mid.x > fminf(t0, THRE_POINT)) ? floorf(p0) : mid.x;
            float o1 = (mid.y > fminf(t1, THRE_POINT)) ? floorf(p1) : mid.y;
            float o2 = (mid.z > fminf(t2, THRE_POINT)) ? floorf(p2) : mid.z;
            float o3 = (mid.w > fminf(t3, THRE_POINT)) ? floorf(p3) : mid.w;

            __stcs(reinterpret_cast<float4*>(out + (size_t)(r0 + ri) * W + c4),
                   make_float4(o0, o1, o2, o3));
        }
    } else {
        // ---------------- boundary path (full checks) ----------------
        float4 arr[RPT + 2];
        float  lft[RPT + 2], rgt[RPT + 2];
#pragma unroll
        for (int s = 0; s < RPT + 2; ++s) {
            int rr = r0 - 1 + s;
            if (rr >= 0 && rr < H)
                arr[s] = *reinterpret_cast<const float4*>(img + (size_t)rr * W + c4);
            else
                arr[s] = make_float4(0.f, 0.f, 0.f, 0.f);
        }
#pragma unroll
        for (int s = 0; s < RPT + 2; ++s) {
            int rr = r0 - 1 + s;
            bool valid = (rr >= 0) && (rr < H);
            float lw = __shfl_up_sync(0xffffffffu, arr[s].w, 1);
            float rw = __shfl_down_sync(0xffffffffu, arr[s].x, 1);
            if (lane == 0)
                lw = (valid && c4 > 0) ? __ldg(img + (size_t)rr * W + c4 - 1) : 0.0f;
            if (lane == 31)
                rw = (valid && c4 + 4 < W) ? __ldg(img + (size_t)rr * W + c4 + 4) : 0.0f;
            lft[s] = lw; rgt[s] = rw;
        }
#pragma unroll
        for (int ri = 0; ri < RPT; ++ri) {
            const int r = r0 + ri;
            const float4 up  = arr[ri];
            const float4 mid = arr[ri + 1];
            const float4 dn  = arr[ri + 2];
            const float lmv = lft[ri + 1], rmv = rgt[ri + 1];

            float hsU[4], hsM[4], hsD[4];
            hsU[0] = lft[ri] + up.x + up.y;  hsU[1] = up.x + up.y + up.z;
            hsU[2] = up.y + up.z + up.w;     hsU[3] = up.z + up.w + rgt[ri];
            hsM[0] = lmv + mid.x + mid.y;    hsM[1] = mid.x + mid.y + mid.z;
            hsM[2] = mid.y + mid.z + mid.w;  hsM[3] = mid.z + mid.w + rmv;
            hsD[0] = lft[ri + 2] + dn.x + dn.y;  hsD[1] = dn.x + dn.y + dn.z;
            hsD[2] = dn.y + dn.z + dn.w;         hsD[3] = dn.z + dn.w + rgt[ri + 2];

            float v[4] = { mid.x, mid.y, mid.z, mid.w };
            float ns[4];
            ns[0] = up.x + dn.x + lmv + mid.y;
            ns[1] = up.y + dn.y + mid.x + mid.z;
            ns[2] = up.z + dn.z + mid.y + mid.w;
            ns[3] = up.w + dn.w + mid.z + rmv;

            const bool rtop = (r == 0), rbot = (r == H - 1);
            const float cnt_row = (float)((r > 0) + (r < H - 1));
            float o[4];
#pragma unroll
            for (int j = 0; j < 4; ++j) {
                int c = c4 + j;
                float sum9 = hsU[j] + hsM[j] + hsD[j];
                float mean = sum9 * (1.0f / 9.0f);
                bool cl = (c == 0), cr = (c == W - 1);
                float coeff = 1.0f;
                if (rtop || rbot || cl || cr)
                    coeff = ((rtop || rbot) && (cl || cr)) ? 2.25f : 1.5f;
                float thr = fminf(THRE_TIMES * mean * coeff, THRE_POINT);
                float cnt = cnt_row + (float)((c > 0) + (c < W - 1));
                float rep = floorf(ns[j] / cnt);
                o[j] = (v[j] > thr) ? rep : v[j];
            }
            __stcs(reinterpret_cast<float4*>(out + (size_t)r * W + c4),
                   make_float4(o[0], o[1], o[2], o[3]));
        }
    }
}

// ---------------------------------------------------------------------------
// Generic fallback for shapes not matching the warp tile.
// ---------------------------------------------------------------------------
__global__ __launch_bounds__(256) void dpr_generic_kernel(
    const float* __restrict__ img, float* __restrict__ out, int H, int W)
{
    const int Wq = (W + 3) >> 2;
    const int qx = blockIdx.x * blockDim.x + threadIdx.x;
    if (qx >= Wq) return;
    const int c4 = qx << 2;
    const int r = blockIdx.y * blockDim.y + threadIdx.y;
    if (r >= H) return;

    float rowv[3][6];
#pragma unroll
    for (int k = 0; k < 3; ++k) {
        int rr = r + k - 1;
        if (rr < 0 || rr >= H) {
#pragma unroll
            for (int j = 0; j < 6; ++j) rowv[k][j] = 0.0f;
        } else {
            const float* p = img + (size_t)rr * W + c4;
#pragma unroll
            for (int j = 0; j < 4; ++j)
                rowv[k][j + 1] = (c4 + j < W) ? p[j] : 0.0f;
            rowv[k][0] = (c4 > 0) ? p[-1] : 0.0f;
            rowv[k][5] = (c4 + 4 < W) ? p[4] : 0.0f;
        }
    }
    const bool rtop = (r == 0), rbot = (r == H - 1);
    const float cnt_row = (float)((r > 0) + (r < H - 1));
#pragma unroll
    for (int j = 0; j < 4; ++j) {
        int c = c4 + j;
        if (c >= W) break;
        float v = rowv[1][j + 1];
        float sum9 = rowv[0][j] + rowv[0][j + 1] + rowv[0][j + 2]
                   + rowv[1][j] + rowv[1][j + 1] + rowv[1][j + 2]
                   + rowv[2][j] + rowv[2][j + 1] + rowv[2][j + 2];
        float mean = sum9 * (1.0f / 9.0f);
        bool cl = (c == 0), cr = (c == W - 1);
        float coeff = 1.0f;
        if (rtop || rbot || cl || cr)
            coeff = ((rtop || rbot) && (cl || cr)) ? 2.25f : 1.5f;
        bool mask = (v > THRE_TIMES * mean * coeff) || (v > THRE_POINT);
        float nsum = rowv[0][j + 1] + rowv[2][j + 1] + rowv[1][j] + rowv[1][j + 2];
        float cnt = cnt_row + (float)((c > 0) + (c < W - 1));
        out[(size_t)r * W + c] = mask ? floorf(nsum / cnt) : v;
    }
}

extern "C" void kernel_launch(void* const* d_in, const int* in_sizes, int n_in,
                              void* d_out, int out_size)
{
    const float* img = (const float*)d_in[0];
    float* out = (float*)d_out;

    int n = in_sizes[0];
    int W = (int)(sqrt((double)n) + 0.5);
    int H = n / W;

    if (W % 128 == 0 && H % (8 * RPT) == 0) {
        dim3 block(32, 8);
        dim3 grid(W / 128, H / (8 * RPT));
        dpr_shfl_kernel<<<grid, block>>>(img, out, H, W);
    } else {
        dim3 block(64, 4);
        dim3 grid(((W + 3) / 4 + block.x - 1) / block.x,
                  (H + block.y - 1) / block.y);
        dpr_generic_kernel<<<grid, block>>>(img, out, H, W);
    }
}

// round 10
// speedup vs baseline: 1.0281x; 1.0281x over previous
#include <cuda_runtime.h>
#include <math.h>

#define THRE_TIMES 5.0f
#define THRE_POINT 1000.0f
#define RPT 4       // output rows per thread
#define BLKY 4      // thread rows per CTA (128-thread CTAs -> 8 CTAs/SM)

typedef unsigned long long u64;

__device__ __forceinline__ u64 pk2(float lo, float hi) {
    u64 r; asm("mov.b64 %0, {%1, %2};" : "=l"(r) : "f"(lo), "f"(hi)); return r;
}
__device__ __forceinline__ void upk2(u64 v, float& lo, float& hi) {
    asm("mov.b64 {%0, %1}, %2;" : "=f"(lo), "=f"(hi) : "l"(v));
}
__device__ __forceinline__ u64 addx2(u64 a, u64 b) {
    u64 r; asm("add.rn.f32x2 %0, %1, %2;" : "=l"(r) : "l"(a), "l"(b)); return r;
}
__device__ __forceinline__ u64 mulx2(u64 a, u64 b) {
    u64 r; asm("mul.rn.f32x2 %0, %1, %2;" : "=l"(r) : "l"(a), "l"(b)); return r;
}

// ---------------------------------------------------------------------------
// Warp = 128 contiguous columns (32 lanes x float4). Halos via shuffle.
// Interior: packed f32x2 math. 128-thread CTAs (8/SM) desynchronize the
// load/compute phases across the SM to smooth DRAM demand.
// Requires W % 128 == 0, H % (BLKY*RPT) == 0.
// ---------------------------------------------------------------------------
__global__ __launch_bounds__(32 * BLKY, 8) void dpr_shfl_kernel(
    const float* __restrict__ img, float* __restrict__ out, int H, int W)
{
    const int lane = threadIdx.x;                       // 0..31
    const int c4   = (blockIdx.x * 32 + lane) * 4;
    const int r0   = (blockIdx.y * BLKY + threadIdx.y) * RPT;

    const bool fast = (r0 >= 1) && (r0 + RPT + 1 <= H) &&
                      (blockIdx.x > 0) && (blockIdx.x < gridDim.x - 1);

    if (fast) {
        // ---------------- interior fast path ----------------
        float4 arr[RPT + 2];
        float  lft[RPT + 2], rgt[RPT + 2];
        const float* base = img + (size_t)(r0 - 1) * W + c4;

        // Edge-lane halo loads first: independent, overlap with the batch below.
        float eh[RPT + 2];
        if (lane == 0) {
#pragma unroll
            for (int s = 0; s < RPT + 2; ++s) eh[s] = __ldg(base + (size_t)s * W - 1);
        } else if (lane == 31) {
#pragma unroll
            for (int s = 0; s < RPT + 2; ++s) eh[s] = __ldg(base + (size_t)s * W + 4);
        }

#pragma unroll
        for (int s = 0; s < RPT + 2; ++s)
            arr[s] = *reinterpret_cast<const float4*>(base + (size_t)s * W);

#pragma unroll
        for (int s = 0; s < RPT + 2; ++s) {
            float lw = __shfl_up_sync(0xffffffffu, arr[s].w, 1);
            float rw = __shfl_down_sync(0xffffffffu, arr[s].x, 1);
            if (lane == 0)  lw = eh[s];
            if (lane == 31) rw = eh[s];
            lft[s] = lw; rgt[s] = rw;
        }

        const u64 PK59  = pk2(THRE_TIMES / 9.0f, THRE_TIMES / 9.0f);  // 5/9
        const u64 PK025 = pk2(0.25f, 0.25f);

#pragma unroll
        for (int ri = 0; ri < RPT; ++ri) {
            const float4 up  = arr[ri];
            const float4 mid = arr[ri + 1];
            const float4 dn  = arr[ri + 2];

            // horizontal 3-sums (packed), built inline from arr/halos
            u64 hsA[3], hsB[3];
#pragma unroll
            for (int k = 0; k < 3; ++k) {
                const float4 a = arr[ri + k];
                u64 yz = pk2(a.y, a.z);
                u64 lx = pk2(lft[ri + k], a.x);
                u64 xy = pk2(a.x, a.y);
                u64 zw = pk2(a.z, a.w);
                u64 wr = pk2(a.w, rgt[ri + k]);
                hsA[k] = addx2(addx2(lx, xy), yz);   // cols 0,1
                hsB[k] = addx2(addx2(yz, zw), wr);   // cols 2,3
            }

            u64 upA = pk2(up.x, up.y),  upB = pk2(up.z, up.w);
            u64 dnA = pk2(dn.x, dn.y),  dnB = pk2(dn.z, dn.w);
            u64 myz = pk2(mid.y, mid.z);

            // ns_j = ((up_j + dn_j) + left_j) + right_j
            u64 nsA = addx2(addx2(addx2(upA, dnA), pk2(lft[ri + 1], mid.x)), myz);
            u64 nsB = addx2(addx2(addx2(upB, dnB), myz), pk2(mid.w, rgt[ri + 1]));

            u64 sum9A = addx2(addx2(hsA[0], hsA[1]), hsA[2]);
            u64 sum9B = addx2(addx2(hsB[0], hsB[1]), hsB[2]);
            u64 thrA = mulx2(sum9A, PK59);
            u64 thrB = mulx2(sum9B, PK59);
            u64 repA = mulx2(nsA, PK025);
            u64 repB = mulx2(nsB, PK025);

            float t0, t1, t2, t3, p0, p1, p2, p3;
            upk2(thrA, t0, t1); upk2(thrB, t2, t3);
            upk2(repA, p0, p1); upk2(repB, p2, p3);

            float o0 = (mid.x > fminf(t0, THRE_POINT)) ? floorf(p0) : mid.x;
            float o1 = (mid.y > fminf(t1, THRE_POINT)) ? floorf(p1) : mid.y;
            float o2 = (mid.z > fminf(t2, THRE_POINT)) ? floorf(p2) : mid.z;
            float o3 = (mid.w > fminf(t3, THRE_POINT)) ? floorf(p3) : mid.w;

            __stcs(reinterpret_cast<float4*>(out + (size_t)(r0 + ri) * W + c4),
                   make_float4(o0, o1, o2, o3));
        }
    } else {
        // ---------------- boundary path (full checks) ----------------
        float4 arr[RPT + 2];
        float  lft[RPT + 2], rgt[RPT + 2];
#pragma unroll
        for (int s = 0; s < RPT + 2; ++s) {
            int rr = r0 - 1 + s;
            if (rr >= 0 && rr < H)
                arr[s] = *reinterpret_cast<const float4*>(img + (size_t)rr * W + c4);
            else
                arr[s] = make_float4(0.f, 0.f, 0.f, 0.f);
        }
#pragma unroll
        for (int s = 0; s < RPT + 2; ++s) {
            int rr = r0 - 1 + s;
            bool valid = (rr >= 0) && (rr < H);
            float lw = __shfl_up_sync(0xffffffffu, arr[s].w, 1);
            float rw = __shfl_down_sync(0xffffffffu, arr[s].x, 1);
            if (lane == 0)
                lw = (valid && c4 > 0) ? __ldg(img + (size_t)rr * W + c4 - 1) : 0.0f;
            if (lane == 31)
                rw = (valid && c4 + 4 < W) ? __ldg(img + (size_t)rr * W + c4 + 4) : 0.0f;
            lft[s] = lw; rgt[s] = rw;
        }
#pragma unroll
        for (int ri = 0; ri < RPT; ++ri) {
            const int r = r0 + ri;
            const float4 up  = arr[ri];
            const float4 mid = arr[ri + 1];
            const float4 dn  = arr[ri + 2];
            const float lmv = lft[ri + 1], rmv = rgt[ri + 1];

            float hsU[4], hsM[4], hsD[4];
            hsU[0] = lft[ri] + up.x + up.y;  hsU[1] = up.x + up.y + up.z;
            hsU[2] = up.y + up.z + up.w;     hsU[3] = up.z + up.w + rgt[ri];
            hsM[0] = lmv + mid.x + mid.y;    hsM[1] = mid.x + mid.y + mid.z;
            hsM[2] = mid.y + mid.z + mid.w;  hsM[3] = mid.z + mid.w + rmv;
            hsD[0] = lft[ri + 2] + dn.x + dn.y;  hsD[1] = dn.x + dn.y + dn.z;
            hsD[2] = dn.y + dn.z + dn.w;         hsD[3] = dn.z + dn.w + rgt[ri + 2];

            float v[4] = { mid.x, mid.y, mid.z, mid.w };
            float ns[4];
            ns[0] = up.x + dn.x + lmv + mid.y;
            ns[1] = up.y + dn.y + mid.x + mid.z;
            ns[2] = up.z + dn.z + mid.y + mid.w;
            ns[3] = up.w + dn.w + mid.z + rmv;

            const bool rtop = (r == 0), rbot = (r == H - 1);
            const float cnt_row = (float)((r > 0) + (r < H - 1));
            float o[4];
#pragma unroll
            for (int j = 0; j < 4; ++j) {
                int c = c4 + j;
                float sum9 = hsU[j] + hsM[j] + hsD[j];
                float mean = sum9 * (1.0f / 9.0f);
                bool cl = (c == 0), cr = (c == W - 1);
                float coeff = 1.0f;
                if (rtop || rbot || cl || cr)
                    coeff = ((rtop || rbot) && (cl || cr)) ? 2.25f : 1.5f;
                float thr = fminf(THRE_TIMES * mean * coeff, THRE_POINT);
                float cnt = cnt_row + (float)((c > 0) + (c < W - 1));
                float rep = floorf(ns[j] / cnt);
                o[j] = (v[j] > thr) ? rep : v[j];
            }
            __stcs(reinterpret_cast<float4*>(out + (size_t)r * W + c4),
                   make_float4(o[0], o[1], o[2], o[3]));
        }
    }
}

// ---------------------------------------------------------------------------
// Generic fallback for shapes not matching the warp tile.
// ---------------------------------------------------------------------------
__global__ __launch_bounds__(256) void dpr_generic_kernel(
    const float* __restrict__ img, float* __restrict__ out, int H, int W)
{
    const int Wq = (W + 3) >> 2;
    const int qx = blockIdx.x * blockDim.x + threadIdx.x;
    if (qx >= Wq) return;
    const int c4 = qx << 2;
    const int r = blockIdx.y * blockDim.y + threadIdx.y;
    if (r >= H) return;

    float rowv[3][6];
#pragma unroll
    for (int k = 0; k < 3; ++k) {
        int rr = r + k - 1;
        if (rr < 0 || rr >= H) {
#pragma unroll
            for (int j = 0; j < 6; ++j) rowv[k][j] = 0.0f;
        } else {
            const float* p = img + (size_t)rr * W + c4;
#pragma unroll
            for (int j = 0; j < 4; ++j)
                rowv[k][j + 1] = (c4 + j < W) ? p[j] : 0.0f;
            rowv[k][0] = (c4 > 0) ? p[-1] : 0.0f;
            rowv[k][5] = (c4 + 4 < W) ? p[4] : 0.0f;
        }
    }
    const bool rtop = (r == 0), rbot = (r == H - 1);
    const float cnt_row = (float)((r > 0) + (r < H - 1));
#pragma unroll
    for (int j = 0; j < 4; ++j) {
        int c = c4 + j;
        if (c >= W) break;
        float v = rowv[1][j + 1];
        float sum9 = rowv[0][j] + rowv[0][j + 1] + rowv[0][j + 2]
                   + rowv[1][j] + rowv[1][j + 1] + rowv[1][j + 2]
                   + rowv[2][j] + rowv[2][j + 1] + rowv[2][j + 2];
        float mean = sum9 * (1.0f / 9.0f);
        bool cl = (c == 0), cr = (c == W - 1);
        float coeff = 1.0f;
        if (rtop || rbot || cl || cr)
            coeff = ((rtop || rbot) && (cl || cr)) ? 2.25f : 1.5f;
        bool mask = (v > THRE_TIMES * mean * coeff) || (v > THRE_POINT);
        float nsum = rowv[0][j + 1] + rowv[2][j + 1] + rowv[1][j] + rowv[1][j + 2];
        float cnt = cnt_row + (float)((c > 0) + (c < W - 1));
        out[(size_t)r * W + c] = mask ? floorf(nsum / cnt) : v;
    }
}

extern "C" void kernel_launch(void* const* d_in, const int* in_sizes, int n_in,
                              void* d_out, int out_size)
{
    const float* img = (const float*)d_in[0];
    float* out = (float*)d_out;

    int n = in_sizes[0];
    int W = (int)(sqrt((double)n) + 0.5);
    int H = n / W;

    if (W % 128 == 0 && H % (BLKY * RPT) == 0) {
        dim3 block(32, BLKY);
        dim3 grid(W / 128, H / (BLKY * RPT));
        dpr_shfl_kernel<<<grid, block>>>(img, out, H, W);
    } else {
        dim3 block(64, 4);
        dim3 grid(((W + 3) / 4 + block.x - 1) / block.x,
                  (H + block.y - 1) / block.y);
        dpr_generic_kernel<<<grid, block>>>(img, out, H, W);
    }
}